// round 10
// baseline (speedup 1.0000x reference)
#include <cuda_runtime.h>
#include <climits>

// Fixed problem shape: B=8, C=1, H=W=768.
#define BB    8
#define HH    768
#define WW    768
#define HWSZ  (HH * WW)          // 589824
#define NTOT  (BB * HWSZ)        // 4718592
#define N4    (NTOT / 4)

#define TS        32
#define TILES_X   24
#define TILES_Y   24
#define NTILES    (BB * TILES_X * TILES_Y)   // 4608

#define EPT   (23 * 768)
#define EPI   (2 * EPT)          // 35328
#define NEDGE (BB * EPI)         // 282624

#define BG16  0xFFFFu
#define ROOT_BLOCKS 512
#define SCALEF 16777216.0f       // 2^24 fixed point: order-invariant sums

// Scratch (static __device__ arrays; allocation-free kernel_launch).
__device__ unsigned g_loc[NTOT];    // packed tile-local roots: pred | (targ<<16)
__device__ int      g_parp[NTOT];   // pred UF parents (tile-root entries only)
__device__ int      g_part[NTOT];   // target UF parents (tile-root entries only)
__device__ int      g_smin[NTOT];   // min target root per pred root (root entries)
__device__ int      g_smax[NTOT];   // max target root per pred root (root entries)
__device__ unsigned long long g_S[NTOT];     // per pred tile-root: fx err-candidate sum
__device__ unsigned long long g_bsum[NTILES];// per-tile fx base sum
__device__ unsigned long long g_esum[ROOT_BLOCKS];
__device__ int      g_rl[NTOT / 2]; // pred tile-root list
__device__ int      g_nrl;          // root count (zeroed by k_flag)
__device__ int      g_flag;         // rescale flag (published fresh each run)
__device__ int      g_neg, g_ctrf;  // k_flag state (zero-init, self-reset)
__device__ int      g_ctr;          // k_root last-block counter (self-reset)

// Exact reference arithmetic for (x + 1.0) * 0.5 without FMA contraction.
__device__ __forceinline__ float resc01(float x) {
    return __fmul_rn(__fadd_rn(x, 1.0f), 0.5f);
}

// ---------------------------------------------------------------------------
// Union-find (min-index rooting; parent <= child invariant)
// ---------------------------------------------------------------------------
__device__ __forceinline__ int uf_find(const int* L, int x) {
    int p = L[x];
    while (p != x) { x = p; p = L[x]; }
    return x;
}

__device__ __forceinline__ int uf_findc(int* L, int x) {   // find + compress
    int r = x, p = L[r];
    while (p != r) { r = p; p = L[r]; }
    while (L[x] != r) { int nx = L[x]; L[x] = r; x = nx; }
    return r;
}

__device__ __forceinline__ void uf_union(int* L, int a, int b) {
    int ra = uf_find(L, a);
    int rb = uf_find(L, b);
    while (ra != rb) {
        int hi = ra > rb ? ra : rb;
        int lo = ra > rb ? rb : ra;
        int old = atomicMin(&L[hi], lo);
        if (old == hi) break;
        ra = lo;
        rb = old;
    }
}

// Shared-memory union-find.
__device__ __forceinline__ int s_find(const int* L, int x) {
    int p = L[x];
    while (p != x) { x = p; p = L[x]; }
    return x;
}

__device__ __forceinline__ void s_union(int* L, int a, int b) {
    int ra = s_find(L, a);
    int rb = s_find(L, b);
    while (ra != rb) {
        int hi = ra > rb ? ra : rb;
        int lo = ra > rb ? rb : ra;
        int old = atomicMin(&L[hi], lo);
        if (old == hi) break;
        ra = lo;
        rb = old;
    }
}

// Reconstruct global index of a tile-local root from tile base index.
__device__ __forceinline__ int rec_root(int base, unsigned loc) {
    return base + (int)(loc >> 5) * WW + (int)(loc & 31u);
}

// ---------------------------------------------------------------------------
// Kernels
// ---------------------------------------------------------------------------
// Publish rescale flag fresh each run; zero root counter (last-block pattern).
__global__ void k_flag(const float4* __restrict__ pred) {
    int i = blockIdx.x * blockDim.x + threadIdx.x;
    float4 v = pred[i];
    bool neg = (v.x < 0.f) | (v.y < 0.f) | (v.z < 0.f) | (v.w < 0.f);
    bool bneg = __syncthreads_or(neg);
    __shared__ bool last;
    if (threadIdx.x == 0) {
        if (bneg) atomicOr(&g_neg, 1);
        __threadfence();
        last = (atomicAdd(&g_ctrf, 1) == (int)gridDim.x - 1);
    }
    __syncthreads();
    if (last && threadIdx.x == 0) {
        g_flag = g_neg; g_neg = 0; g_ctrf = 0;
        g_nrl = 0;
    }
}

// Per 32x32 tile: masks, in-tile CCL, packed local roots, per-component error
// candidate sums (smem u64 fixed point), per-tile base sum, root-list emit.
__global__ void k_tile(const float* __restrict__ pred,
                       const float* __restrict__ target) {
    __shared__ int lp[TS * TS];
    __shared__ int lt[TS * TS];
    __shared__ unsigned long long sS[TS * TS];
    __shared__ unsigned long long sBase[32];
    __shared__ int s_rcnt, s_rbase;

    int lx = threadIdx.x, ly = threadIdx.y;
    int l  = ly * TS + lx;
    int b  = blockIdx.z;
    int gbase = b * HWSZ + blockIdx.y * TS * WW + blockIdx.x * TS;
    int gi = gbase + ly * WW + lx;
    int tileIdx = (b * TILES_Y + blockIdx.y) * TILES_X + blockIdx.x;

    bool  resc = (g_flag != 0);
    float p = pred[gi];
    float t = target[gi];
    float pp  = resc ? resc01(p) : p;
    float t01 = resc01(t);
    bool mp = pp  > 0.5f;
    bool mt = t01 > 0.5f;
    float pl = fabsf(pp - t01);
    unsigned long long fx = __float2ull_rn(pl * SCALEF);

    lp[l] = mp ? l : -1;
    lt[l] = mt ? l : -1;
    sS[l] = 0ull;
    if (l == 0) s_rcnt = 0;

    // Per-warp base-sum reduction (u64 => order-invariant / deterministic).
    {
        unsigned long long w = fx;
        #pragma unroll
        for (int off = 16; off > 0; off >>= 1)
            w += __shfl_down_sync(0xffffffffu, w, off);
        if (lx == 0) sBase[ly] = w;
    }
    __syncthreads();

    if (mp) {
        if (lx > 0 && lp[l - 1]  >= 0) s_union(lp, l, l - 1);
        if (ly > 0 && lp[l - TS] >= 0) s_union(lp, l, l - TS);
    }
    if (mt) {
        if (lx > 0 && lt[l - 1]  >= 0) s_union(lt, l, l - 1);
        if (ly > 0 && lt[l - TS] >= 0) s_union(lt, l, l - TS);
    }
    __syncthreads();

    int rp = mp ? s_find(lp, l) : -1;
    int rt = mt ? s_find(lt, l) : -1;
    if (mp && !mt) atomicAdd(&sS[rp], fx);   // integer: order-invariant
    __syncthreads();

    unsigned rp16 = BG16, rt16 = BG16;
    bool rootp = false;
    if (mp) {
        rp16 = (unsigned)rp;
        if (rp == l) {
            rootp = true;
            g_parp[gi] = gi;
            g_smin[gi] = INT_MAX;
            g_smax[gi] = -1;
            g_S[gi]    = sS[l];
        }
    }
    if (mt) {
        rt16 = (unsigned)rt;
        if (rt == l) g_part[gi] = gi;
    }
    g_loc[gi] = rp16 | (rt16 << 16);

    // Root-list compaction: warp-aggregated slot reservation.
    {
        unsigned bal = __ballot_sync(0xffffffffu, rootp);
        int cnt = __popc(bal);
        int base = 0;
        if (cnt) {
            if (lx == __ffs(bal) - 1) base = atomicAdd(&s_rcnt, cnt);
            base = __shfl_sync(0xffffffffu, base, __ffs(bal) - 1);
        }
        __syncthreads();
        if (l == 0) s_rbase = s_rcnt ? atomicAdd(&g_nrl, s_rcnt) : 0;
        // Tile base sum: warp partials -> one lane, plain store.
        if (l == 32) {   // warp 1 lane 0 sums while warp 0 lane 0 idles on s_rbase
            unsigned long long tb = 0ull;
            #pragma unroll
            for (int k = 0; k < 32; k++) tb += sBase[k];
            g_bsum[tileIdx] = tb;
        }
        __syncthreads();
        if (rootp) g_rl[s_rbase + base + __popc(bal & ((1u << lx) - 1))] = gi;
    }
}

// Merge across tile boundaries; one thread = one edge, handles both masks.
__global__ void k_bmerge() {
    int tid = blockIdx.x * blockDim.x + threadIdx.x;
    if (tid >= NEDGE) return;
    int b = tid / EPI;
    int e = tid % EPI;
    int y, x, ny, nx;
    if (e < EPT) {                       // vertical boundary: (y,x)-(y,x-1)
        int bi = e / HH; y = e % HH;
        x = TS * (bi + 1); ny = y; nx = x - 1;
    } else {                             // horizontal boundary: (y,x)-(y-1,x)
        e -= EPT;
        int bi = e / WW; x = e % WW;
        y = TS * (bi + 1); ny = y - 1; nx = x;
    }
    int idx = b * HWSZ + y * WW + x;
    int n   = b * HWSZ + ny * WW + nx;
    unsigned a = g_loc[idx], c = g_loc[n];
    int abase = b * HWSZ + (y  & ~31) * WW + (x  & ~31);
    int cbase = b * HWSZ + (ny & ~31) * WW + (nx & ~31);

    if ((a & BG16) != BG16 && (c & BG16) != BG16)
        uf_union(g_parp, rec_root(abase, a & BG16), rec_root(cbase, c & BG16));
    if ((a >> 16) != BG16 && (c >> 16) != BG16)
        uf_union(g_part, rec_root(abase, a >> 16), rec_root(cbase, c >> 16));
}

// Per pixel: compressing chases on overlap pixels feed smin/smax atomics.
__global__ void k_agg() {
    int i = blockIdx.x * blockDim.x + threadIdx.x;   // exact cover of NTOT
    unsigned v = g_loc[i];
    unsigned pl = v & BG16, tl = v >> 16;
    if (pl == BG16 || tl == BG16) return;
    int rem  = i % HWSZ;
    int base = (i - rem) + ((rem / WW) & ~31) * WW + ((rem % WW) & ~31);
    int rp = uf_findc(g_parp, rec_root(base, pl));
    int rt = uf_findc(g_part, rec_root(base, tl));
    atomicMin(&g_smin[rp], rt);
    atomicMax(&g_smax[rp], rt);
}

// Per pred tile-root: merged? -> add S. Fused deterministic final reduction.
__global__ void k_root(float* __restrict__ out) {
    __shared__ unsigned long long shu[256];
    int n = g_nrl;
    unsigned long long es = 0ull;
    for (int i = blockIdx.x * blockDim.x + threadIdx.x; i < n;
         i += gridDim.x * blockDim.x) {
        int r = g_rl[i];
        int R = uf_find(g_parp, r);      // short: paths compressed by k_agg
        if (g_smax[R] > g_smin[R]) es += g_S[r];
    }
    shu[threadIdx.x] = es;
    __syncthreads();
    for (int off = 128; off > 0; off >>= 1) {
        if (threadIdx.x < off) shu[threadIdx.x] += shu[threadIdx.x + off];
        __syncthreads();
    }
    __shared__ bool last;
    if (threadIdx.x == 0) {
        g_esum[blockIdx.x] = shu[0];
        __threadfence();
        last = (atomicAdd(&g_ctr, 1) == (int)gridDim.x - 1);
    }
    __syncthreads();

    if (last) {
        unsigned long long acc = 0ull;
        for (int k = threadIdx.x; k < NTILES; k += 256) acc += g_bsum[k];
        for (int k = threadIdx.x; k < ROOT_BLOCKS; k += 256) {
            unsigned long long e10 = g_esum[k];
            acc += e10 * 10ull;          // err term carries weight 10
        }
        shu[threadIdx.x] = acc;
        __syncthreads();
        for (int off = 128; off > 0; off >>= 1) {
            if (threadIdx.x < off) shu[threadIdx.x] += shu[threadIdx.x + off];
            __syncthreads();
        }
        if (threadIdx.x == 0) {
            double total = (double)shu[0] / (double)SCALEF;
            out[0] = (float)(total / (double)NTOT);
            g_ctr = 0;                   // reset for next replay
        }
    }
}

// ---------------------------------------------------------------------------
extern "C" void kernel_launch(void* const* d_in, const int* in_sizes, int n_in,
                              void* d_out, int out_size) {
    const float* pred   = (const float*)d_in[0];
    const float* target = (const float*)d_in[1];
    float* out = (float*)d_out;

    k_flag<<<N4 / 256, 256>>>((const float4*)pred);
    k_tile<<<dim3(TILES_X, TILES_Y, BB), dim3(TS, TS)>>>(pred, target);
    k_bmerge<<<(NEDGE + 255) / 256, 256>>>();
    k_agg<<<NTOT / 256, 256>>>();
    k_root<<<ROOT_BLOCKS, 256>>>(out);
}

// round 11
// speedup vs baseline: 1.2766x; 1.2766x over previous
#include <cuda_runtime.h>
#include <climits>

// Fixed problem shape: B=8, C=1, H=W=768.
#define BB    8
#define HH    768
#define WW    768
#define HWSZ  (HH * WW)          // 589824
#define NTOT  (BB * HWSZ)        // 4718592
#define N4    (NTOT / 4)         // 1179648

#define TS        32
#define TILES_X   24
#define TILES_Y   24
#define NTILES    (BB * TILES_X * TILES_Y)   // 4608

#define EPT   (23 * 768)
#define EPI   (2 * EPT)          // 35328
#define NEDGE (BB * EPI)         // 282624

#define BG16  0xFFFFu
#define MAXR  (NTOT / 2)         // hard cap on roots per mask (512/tile max)
#define LOSS_BLOCKS (N4 / 256)   // 4608

// Scratch (static __device__ arrays; allocation-free kernel_launch).
__device__ unsigned g_loc[NTOT];      // packed per-pixel root RANKS: pred | targ<<16
__device__ int      g_pbase[NTILES];  // compact-ID base per tile (pred)
__device__ int      g_tbase[NTILES];  // compact-ID base per tile (target)
__device__ int      g_parp[MAXR];     // pred UF parents over compact IDs (~1.2MB live)
__device__ int      g_part[MAXR];     // target UF parents over compact IDs
__device__ int      g_smin[MAXR];     // min target ID per pred root
__device__ int      g_smax[MAXR];     // max target ID per pred root
__device__ int      g_np, g_nt;       // compact-ID counters (reset by k_flag)
__device__ int      g_flag;           // rescale flag (published fresh each run)
__device__ int      g_neg, g_ctrf;    // k_flag state (zero-init, self-reset)
__device__ int      g_ctr;            // k_loss last-block counter (self-reset)
__device__ double   g_psum[LOSS_BLOCKS];

// Exact reference arithmetic for (x + 1.0) * 0.5 without FMA contraction.
__device__ __forceinline__ float resc01(float x) {
    return __fmul_rn(__fadd_rn(x, 1.0f), 0.5f);
}

// ---------------------------------------------------------------------------
// Union-find over compact IDs (min-ID rooting; parent <= child invariant)
// ---------------------------------------------------------------------------
__device__ __forceinline__ int uf_find(const int* L, int x) {
    int p = L[x];
    while (p != x) { x = p; p = L[x]; }
    return x;
}

__device__ __forceinline__ int uf_findc(int* L, int x) {   // find + compress
    int r = x, p = L[r];
    while (p != r) { r = p; p = L[r]; }
    while (L[x] != r) { int nx = L[x]; L[x] = r; x = nx; }
    return r;
}

__device__ __forceinline__ void uf_union(int* L, int a, int b) {
    int ra = uf_find(L, a);
    int rb = uf_find(L, b);
    while (ra != rb) {
        int hi = ra > rb ? ra : rb;
        int lo = ra > rb ? rb : ra;
        int old = atomicMin(&L[hi], lo);
        if (old == hi) break;
        ra = lo;
        rb = old;
    }
}

// Shared-memory union-find (tile-local labels).
__device__ __forceinline__ int s_find(const int* L, int x) {
    int p = L[x];
    while (p != x) { x = p; p = L[x]; }
    return x;
}

__device__ __forceinline__ void s_union(int* L, int a, int b) {
    int ra = s_find(L, a);
    int rb = s_find(L, b);
    while (ra != rb) {
        int hi = ra > rb ? ra : rb;
        int lo = ra > rb ? rb : ra;
        int old = atomicMin(&L[hi], lo);
        if (old == hi) break;
        ra = lo;
        rb = old;
    }
}

// ---------------------------------------------------------------------------
// Kernels
// ---------------------------------------------------------------------------
// Publish rescale flag fresh each run; reset compact-ID counters before k_tile.
__global__ void k_flag(const float4* __restrict__ pred) {
    int i = blockIdx.x * blockDim.x + threadIdx.x;
    float4 v = pred[i];
    bool neg = (v.x < 0.f) | (v.y < 0.f) | (v.z < 0.f) | (v.w < 0.f);
    bool bneg = __syncthreads_or(neg);
    __shared__ bool last;
    if (threadIdx.x == 0) {
        if (bneg) atomicOr(&g_neg, 1);
        __threadfence();
        last = (atomicAdd(&g_ctrf, 1) == (int)gridDim.x - 1);
    }
    __syncthreads();
    if (last && threadIdx.x == 0) {
        g_flag = g_neg; g_neg = 0; g_ctrf = 0;
        g_np = 0; g_nt = 0;
    }
}

// Per 32x32 tile: masks, in-tile CCL, compact-ID assignment (ballot prefix +
// one global atomicAdd per mask), packed rank labels, compact UF/minmax init.
__global__ void k_tile(const float* __restrict__ pred,
                       const float* __restrict__ target) {
    __shared__ int lp[TS * TS];
    __shared__ int lt[TS * TS];
    __shared__ int sWp[32], sWt[32];
    __shared__ int s_pb, s_tb;

    int lx = threadIdx.x, ly = threadIdx.y;
    int l  = ly * TS + lx;
    int b  = blockIdx.z;
    int gi = b * HWSZ + (blockIdx.y * TS + ly) * WW + blockIdx.x * TS + lx;
    int tileIdx = (b * TILES_Y + blockIdx.y) * TILES_X + blockIdx.x;

    bool  resc = (g_flag != 0);
    float p = pred[gi];
    float t = target[gi];
    float pp  = resc ? resc01(p) : p;
    float t01 = resc01(t);
    bool mp = pp  > 0.5f;
    bool mt = t01 > 0.5f;

    lp[l] = mp ? l : -1;
    lt[l] = mt ? l : -1;
    __syncthreads();

    if (mp) {
        if (lx > 0 && lp[l - 1]  >= 0) s_union(lp, l, l - 1);
        if (ly > 0 && lp[l - TS] >= 0) s_union(lp, l, l - TS);
    }
    if (mt) {
        if (lx > 0 && lt[l - 1]  >= 0) s_union(lt, l, l - 1);
        if (ly > 0 && lt[l - TS] >= 0) s_union(lt, l, l - TS);
    }
    __syncthreads();

    int rp = mp ? s_find(lp, l) : -1;
    int rt = mt ? s_find(lt, l) : -1;
    bool rootp = mp && (rp == l);
    bool roott = mt && (rt == l);

    unsigned balp = __ballot_sync(0xffffffffu, rootp);
    unsigned balt = __ballot_sync(0xffffffffu, roott);
    if (lx == 0) { sWp[ly] = __popc(balp); sWt[ly] = __popc(balt); }
    __syncthreads();

    // Exclusive scan of per-warp root counts; warp 0 = pred, warp 1 = target.
    if (l < 32) {
        int orig = sWp[l], v = orig;
        #pragma unroll
        for (int o = 1; o < 32; o <<= 1) {
            int n = __shfl_up_sync(0xffffffffu, v, o);
            if (l >= o) v += n;
        }
        sWp[l] = v - orig;
        if (l == 31) s_pb = atomicAdd(&g_np, v);
    } else if (l < 64) {
        int k = l - 32;
        int orig = sWt[k], v = orig;
        #pragma unroll
        for (int o = 1; o < 32; o <<= 1) {
            int n = __shfl_up_sync(0xffffffffu, v, o);
            if (k >= o) v += n;
        }
        sWt[k] = v - orig;
        if (k == 31) s_tb = atomicAdd(&g_nt, v);
    }
    __syncthreads();

    // Roots: compute rank, init compact entries, publish rank via lp/lt[l].
    unsigned lmask = (1u << lx) - 1u;
    if (rootp) {
        int rank = sWp[ly] + __popc(balp & lmask);
        int cid  = s_pb + rank;
        lp[l] = rank;
        g_parp[cid] = cid;
        g_smin[cid] = INT_MAX;
        g_smax[cid] = -1;
    }
    if (roott) {
        int rank = sWt[ly] + __popc(balt & lmask);
        lt[l] = rank;
        g_part[s_tb + rank] = s_tb + rank;
    }
    __syncthreads();

    unsigned pr16 = mp ? (unsigned)lp[rp] : BG16;
    unsigned tr16 = mt ? (unsigned)lt[rt] : BG16;
    g_loc[gi] = pr16 | (tr16 << 16);
    if (l == 0) { g_pbase[tileIdx] = s_pb; g_tbase[tileIdx] = s_tb; }
}

// Merge across tile boundaries; one thread = one edge, both masks.
// All UF traffic hits the compact (~1.2MB live) arrays -> L2-resident.
__global__ void k_bmerge() {
    int tid = blockIdx.x * blockDim.x + threadIdx.x;
    if (tid >= NEDGE) return;
    int b = tid / EPI;
    int e = tid % EPI;
    int y, x, ny, nx;
    if (e < EPT) {                       // vertical boundary: (y,x)-(y,x-1)
        int bi = e / HH; y = e % HH;
        x = TS * (bi + 1); ny = y; nx = x - 1;
    } else {                             // horizontal boundary: (y,x)-(y-1,x)
        e -= EPT;
        int bi = e / WW; x = e % WW;
        y = TS * (bi + 1); ny = y - 1; nx = x;
    }
    int idx = b * HWSZ + y * WW + x;
    int n   = b * HWSZ + ny * WW + nx;
    unsigned a = g_loc[idx], c = g_loc[n];
    int tA = (b * TILES_Y + (y  >> 5)) * TILES_X + (x  >> 5);
    int tC = (b * TILES_Y + (ny >> 5)) * TILES_X + (nx >> 5);

    if ((a & BG16) != BG16 && (c & BG16) != BG16)
        uf_union(g_parp, g_pbase[tA] + (int)(a & BG16),
                          g_pbase[tC] + (int)(c & BG16));
    if ((a >> 16) != BG16 && (c >> 16) != BG16)
        uf_union(g_part, g_tbase[tA] + (int)(a >> 16),
                          g_tbase[tC] + (int)(c >> 16));
}

// Per pixel: overlap pixels chase (compressing) L2-resident parents and feed
// L2-resident min/max atomics.
__global__ void k_agg() {
    int i = blockIdx.x * blockDim.x + threadIdx.x;   // exact cover of NTOT
    unsigned v = g_loc[i];
    unsigned pl = v & BG16, tl = v >> 16;
    if (pl == BG16 || tl == BG16) return;
    int b   = i / HWSZ;
    int rem = i - b * HWSZ;
    int tile = (b * TILES_Y + ((rem / WW) >> 5)) * TILES_X + ((rem % WW) >> 5);
    int rp = uf_findc(g_parp, g_pbase[tile] + (int)pl);
    int rt = uf_findc(g_part, g_tbase[tile] + (int)tl);
    atomicMin(&g_smin[rp], rt);
    atomicMax(&g_smax[rp], rt);
}

// Weighted loss + fused deterministic final reduction (last-block pattern).
__global__ void k_loss(const float4* __restrict__ pred,
                       const float4* __restrict__ target,
                       float* __restrict__ out) {
    __shared__ double sh[256];
    bool resc = (g_flag != 0);
    int v = blockIdx.x * blockDim.x + threadIdx.x;   // exact cover of N4
    int i0  = 4 * v;
    int b   = i0 / HWSZ;
    int rem = i0 - b * HWSZ;
    int tile = (b * TILES_Y + ((rem / WW) >> 5)) * TILES_X + ((rem % WW) >> 5);
    int pbase = g_pbase[tile];   // all 4 pixels share one tile (x0 % 4 == 0)

    float4 p = pred[v];
    float4 t = target[v];
    uint4  L = ((const uint4*)g_loc)[v];
    float pv[4] = {p.x, p.y, p.z, p.w};
    float tv[4] = {t.x, t.y, t.z, t.w};
    unsigned lv[4] = {L.x, L.y, L.z, L.w};

    double s = 0.0;
    #pragma unroll
    for (int j = 0; j < 4; j++) {
        float pp  = resc ? resc01(pv[j]) : pv[j];
        float t01 = resc01(tv[j]);
        float pl  = fabsf(pp - t01);
        float w   = 1.0f;
        unsigned lr = lv[j] & BG16;
        if (lr != BG16 && !(t01 > 0.5f)) {        // pred fg, target bg
            int R = pbase + (int)lr;               // chase L2-resident parents
            int P = g_parp[R];
            while (P != R) { R = P; P = g_parp[R]; }
            if (g_smax[R] > g_smin[R]) w = 11.0f;  // merged component
        }
        s += (double)(pl * w);
    }

    sh[threadIdx.x] = s;
    __syncthreads();
    for (int off = 128; off > 0; off >>= 1) {
        if (threadIdx.x < off) sh[threadIdx.x] += sh[threadIdx.x + off];
        __syncthreads();
    }
    __shared__ bool last;
    if (threadIdx.x == 0) {
        g_psum[blockIdx.x] = sh[0];
        __threadfence();
        last = (atomicAdd(&g_ctr, 1) == (int)gridDim.x - 1);
    }
    __syncthreads();

    if (last) {
        double s2 = 0.0;
        for (int k = 0; k < LOSS_BLOCKS / 256; k++)          // fixed order
            s2 += g_psum[threadIdx.x + 256 * k];
        sh[threadIdx.x] = s2;
        __syncthreads();
        for (int off = 128; off > 0; off >>= 1) {
            if (threadIdx.x < off) sh[threadIdx.x] += sh[threadIdx.x + off];
            __syncthreads();
        }
        if (threadIdx.x == 0) {
            out[0] = (float)(sh[0] / (double)NTOT);
            g_ctr = 0;                                       // reset for replay
        }
    }
}

// ---------------------------------------------------------------------------
extern "C" void kernel_launch(void* const* d_in, const int* in_sizes, int n_in,
                              void* d_out, int out_size) {
    const float* pred   = (const float*)d_in[0];
    const float* target = (const float*)d_in[1];
    float* out = (float*)d_out;

    k_flag<<<N4 / 256, 256>>>((const float4*)pred);
    k_tile<<<dim3(TILES_X, TILES_Y, BB), dim3(TS, TS)>>>(pred, target);
    k_bmerge<<<(NEDGE + 255) / 256, 256>>>();
    k_agg<<<NTOT / 256, 256>>>();
    k_loss<<<LOSS_BLOCKS, 256>>>((const float4*)pred, (const float4*)target, out);
}

// round 12
// speedup vs baseline: 1.3680x; 1.0716x over previous
#include <cuda_runtime.h>
#include <climits>

// Fixed problem shape: B=8, C=1, H=W=768.
#define BB    8
#define HH    768
#define WW    768
#define HWSZ  (HH * WW)          // 589824
#define NTOT  (BB * HWSZ)        // 4718592
#define N4    (NTOT / 4)         // 1179648

#define TS        32
#define TILES_X   24
#define TILES_Y   24
#define NTILES    (BB * TILES_X * TILES_Y)   // 4608

#define EPT   (23 * 768)
#define EPI   (2 * EPT)          // 35328
#define NEDGE (BB * EPI)         // 282624

#define BG16  0xFFFFu
#define MAXR  (NTOT / 2)         // hard cap on roots per mask
#define LOSS_BLOCKS (N4 / 256)   // 4608
#define COMP_BLOCKS 1024

// Scratch (static __device__ arrays; allocation-free kernel_launch).
__device__ unsigned g_loc[NTOT];      // packed per-pixel root RANKS: pred | targ<<16
__device__ int      g_pbase[NTILES];  // compact-ID base per tile (pred)
__device__ int      g_tbase[NTILES];  // compact-ID base per tile (target)
__device__ int      g_parp[MAXR];     // pred UF parents over compact IDs (L2-resident live set)
__device__ int      g_part[MAXR];     // target UF parents over compact IDs
__device__ int      g_smin[MAXR];     // min target ID per pred root
__device__ int      g_smax[MAXR];     // max target ID per pred root
__device__ int      g_np, g_nt;       // compact-ID counters (reset by k_flag)
__device__ int      g_flag;           // rescale flag (published fresh each run)
__device__ int      g_neg, g_ctrf;    // k_flag state (zero-init, self-reset)
__device__ int      g_ctr;            // k_loss last-block counter (self-reset)
__device__ double   g_psum[LOSS_BLOCKS];

// Exact reference arithmetic for (x + 1.0) * 0.5 without FMA contraction.
__device__ __forceinline__ float resc01(float x) {
    return __fmul_rn(__fadd_rn(x, 1.0f), 0.5f);
}

// ---------------------------------------------------------------------------
// Union-find over compact IDs (min-ID rooting; parent <= child invariant)
// ---------------------------------------------------------------------------
__device__ __forceinline__ int uf_find(const int* L, int x) {
    int p = L[x];
    while (p != x) { x = p; p = L[x]; }
    return x;
}

__device__ __forceinline__ int uf_findc(int* L, int x) {   // find + compress
    int r = x, p = L[r];
    while (p != r) { r = p; p = L[r]; }
    while (L[x] != r) { int nx = L[x]; L[x] = r; x = nx; }
    return r;
}

__device__ __forceinline__ void uf_union(int* L, int a, int b) {
    int ra = uf_find(L, a);
    int rb = uf_find(L, b);
    while (ra != rb) {
        int hi = ra > rb ? ra : rb;
        int lo = ra > rb ? rb : ra;
        int old = atomicMin(&L[hi], lo);
        if (old == hi) break;
        ra = lo;
        rb = old;
    }
}

// Shared-memory union-find (tile-local labels).
__device__ __forceinline__ int s_find(const int* L, int x) {
    int p = L[x];
    while (p != x) { x = p; p = L[x]; }
    return x;
}

__device__ __forceinline__ void s_union(int* L, int a, int b) {
    int ra = s_find(L, a);
    int rb = s_find(L, b);
    while (ra != rb) {
        int hi = ra > rb ? ra : rb;
        int lo = ra > rb ? rb : ra;
        int old = atomicMin(&L[hi], lo);
        if (old == hi) break;
        ra = lo;
        rb = old;
    }
}

// ---------------------------------------------------------------------------
// Kernels
// ---------------------------------------------------------------------------
// Publish rescale flag fresh each run; reset compact-ID counters before k_tile.
__global__ void k_flag(const float4* __restrict__ pred) {
    int i = blockIdx.x * blockDim.x + threadIdx.x;
    float4 v = pred[i];
    bool neg = (v.x < 0.f) | (v.y < 0.f) | (v.z < 0.f) | (v.w < 0.f);
    bool bneg = __syncthreads_or(neg);
    __shared__ bool last;
    if (threadIdx.x == 0) {
        if (bneg) atomicOr(&g_neg, 1);
        __threadfence();
        last = (atomicAdd(&g_ctrf, 1) == (int)gridDim.x - 1);
    }
    __syncthreads();
    if (last && threadIdx.x == 0) {
        g_flag = g_neg; g_neg = 0; g_ctrf = 0;
        g_np = 0; g_nt = 0;
    }
}

// Per 32x32 tile: masks, in-tile CCL, compact-ID assignment (ballot prefix +
// one global atomicAdd per mask), packed rank labels, compact UF/minmax init.
__global__ void k_tile(const float* __restrict__ pred,
                       const float* __restrict__ target) {
    __shared__ int lp[TS * TS];
    __shared__ int lt[TS * TS];
    __shared__ int sWp[32], sWt[32];
    __shared__ int s_pb, s_tb;

    int lx = threadIdx.x, ly = threadIdx.y;
    int l  = ly * TS + lx;
    int b  = blockIdx.z;
    int gi = b * HWSZ + (blockIdx.y * TS + ly) * WW + blockIdx.x * TS + lx;
    int tileIdx = (b * TILES_Y + blockIdx.y) * TILES_X + blockIdx.x;

    bool  resc = (g_flag != 0);
    float p = pred[gi];
    float t = target[gi];
    float pp  = resc ? resc01(p) : p;
    float t01 = resc01(t);
    bool mp = pp  > 0.5f;
    bool mt = t01 > 0.5f;

    lp[l] = mp ? l : -1;
    lt[l] = mt ? l : -1;
    __syncthreads();

    if (mp) {
        if (lx > 0 && lp[l - 1]  >= 0) s_union(lp, l, l - 1);
        if (ly > 0 && lp[l - TS] >= 0) s_union(lp, l, l - TS);
    }
    if (mt) {
        if (lx > 0 && lt[l - 1]  >= 0) s_union(lt, l, l - 1);
        if (ly > 0 && lt[l - TS] >= 0) s_union(lt, l, l - TS);
    }
    __syncthreads();

    int rp = mp ? s_find(lp, l) : -1;
    int rt = mt ? s_find(lt, l) : -1;
    bool rootp = mp && (rp == l);
    bool roott = mt && (rt == l);

    unsigned balp = __ballot_sync(0xffffffffu, rootp);
    unsigned balt = __ballot_sync(0xffffffffu, roott);
    if (lx == 0) { sWp[ly] = __popc(balp); sWt[ly] = __popc(balt); }
    __syncthreads();

    // Exclusive scan of per-warp root counts; warp 0 = pred, warp 1 = target.
    if (l < 32) {
        int orig = sWp[l], v = orig;
        #pragma unroll
        for (int o = 1; o < 32; o <<= 1) {
            int n = __shfl_up_sync(0xffffffffu, v, o);
            if (l >= o) v += n;
        }
        sWp[l] = v - orig;
        if (l == 31) s_pb = atomicAdd(&g_np, v);
    } else if (l < 64) {
        int k = l - 32;
        int orig = sWt[k], v = orig;
        #pragma unroll
        for (int o = 1; o < 32; o <<= 1) {
            int n = __shfl_up_sync(0xffffffffu, v, o);
            if (k >= o) v += n;
        }
        sWt[k] = v - orig;
        if (k == 31) s_tb = atomicAdd(&g_nt, v);
    }
    __syncthreads();

    // Roots: compute rank, init compact entries, publish rank via lp/lt[l].
    unsigned lmask = (1u << lx) - 1u;
    if (rootp) {
        int rank = sWp[ly] + __popc(balp & lmask);
        int cid  = s_pb + rank;
        lp[l] = rank;
        g_parp[cid] = cid;
        g_smin[cid] = INT_MAX;
        g_smax[cid] = -1;
    }
    if (roott) {
        int rank = sWt[ly] + __popc(balt & lmask);
        lt[l] = rank;
        g_part[s_tb + rank] = s_tb + rank;
    }
    __syncthreads();

    unsigned pr16 = mp ? (unsigned)lp[rp] : BG16;
    unsigned tr16 = mt ? (unsigned)lt[rt] : BG16;
    g_loc[gi] = pr16 | (tr16 << 16);
    if (l == 0) { g_pbase[tileIdx] = s_pb; g_tbase[tileIdx] = s_tb; }
}

// Merge across tile boundaries; one thread = one edge, both masks.
// All UF traffic hits the compact (L2-resident) arrays.
__global__ void k_bmerge() {
    int tid = blockIdx.x * blockDim.x + threadIdx.x;
    if (tid >= NEDGE) return;
    int b = tid / EPI;
    int e = tid % EPI;
    int y, x, ny, nx;
    if (e < EPT) {                       // vertical boundary: (y,x)-(y,x-1)
        int bi = e / HH; y = e % HH;
        x = TS * (bi + 1); ny = y; nx = x - 1;
    } else {                             // horizontal boundary: (y,x)-(y-1,x)
        e -= EPT;
        int bi = e / WW; x = e % WW;
        y = TS * (bi + 1); ny = y - 1; nx = x;
    }
    int idx = b * HWSZ + y * WW + x;
    int n   = b * HWSZ + ny * WW + nx;
    unsigned a = g_loc[idx], c = g_loc[n];
    int tA = (b * TILES_Y + (y  >> 5)) * TILES_X + (x  >> 5);
    int tC = (b * TILES_Y + (ny >> 5)) * TILES_X + (nx >> 5);

    if ((a & BG16) != BG16 && (c & BG16) != BG16)
        uf_union(g_parp, g_pbase[tA] + (int)(a & BG16),
                          g_pbase[tC] + (int)(c & BG16));
    if ((a >> 16) != BG16 && (c >> 16) != BG16)
        uf_union(g_part, g_tbase[tA] + (int)(a >> 16),
                          g_tbase[tC] + (int)(c >> 16));
}

// Flatten EVERY live compact entry to its final root. With compact IDs, the
// live sets are exactly [0, g_np) and [0, g_nt): no lists, no bitmaps.
// Each thread: one independent short chase over L2-resident data -> high MLP.
__global__ void k_compress() {
    int np = g_np, nt = g_nt;
    int total = np + nt;
    for (int i = blockIdx.x * blockDim.x + threadIdx.x; i < total;
         i += gridDim.x * blockDim.x) {
        if (i < np) uf_findc(g_parp, i);
        else        uf_findc(g_part, i - np);
    }
}

// Per pixel: overlap pixels resolve final roots with ONE load each (entries
// pre-flattened by k_compress) and feed L2-resident min/max atomics.
__global__ void k_agg() {
    int i = blockIdx.x * blockDim.x + threadIdx.x;   // exact cover of NTOT
    unsigned v = g_loc[i];
    unsigned pl = v & BG16, tl = v >> 16;
    if (pl == BG16 || tl == BG16) return;
    int b   = i / HWSZ;
    int rem = i - b * HWSZ;
    int tile = (b * TILES_Y + ((rem / WW) >> 5)) * TILES_X + ((rem % WW) >> 5);
    int rp = g_parp[g_pbase[tile] + (int)pl];   // 1 hop: flattened
    int rt = g_part[g_tbase[tile] + (int)tl];   // 1 hop: flattened
    atomicMin(&g_smin[rp], rt);
    atomicMax(&g_smax[rp], rt);
}

// Weighted loss + fused deterministic final reduction (last-block pattern).
__global__ void k_loss(const float4* __restrict__ pred,
                       const float4* __restrict__ target,
                       float* __restrict__ out) {
    __shared__ double sh[256];
    bool resc = (g_flag != 0);
    int v = blockIdx.x * blockDim.x + threadIdx.x;   // exact cover of N4
    int i0  = 4 * v;
    int b   = i0 / HWSZ;
    int rem = i0 - b * HWSZ;
    int tile = (b * TILES_Y + ((rem / WW) >> 5)) * TILES_X + ((rem % WW) >> 5);
    int pbase = g_pbase[tile];   // all 4 pixels share one tile (x0 % 4 == 0)

    float4 p = pred[v];
    float4 t = target[v];
    uint4  L = ((const uint4*)g_loc)[v];
    float pv[4] = {p.x, p.y, p.z, p.w};
    float tv[4] = {t.x, t.y, t.z, t.w};
    unsigned lv[4] = {L.x, L.y, L.z, L.w};

    double s = 0.0;
    #pragma unroll
    for (int j = 0; j < 4; j++) {
        float pp  = resc ? resc01(pv[j]) : pv[j];
        float t01 = resc01(tv[j]);
        float pl  = fabsf(pp - t01);
        float w   = 1.0f;
        unsigned lr = lv[j] & BG16;
        if (lr != BG16 && !(t01 > 0.5f)) {        // pred fg, target bg
            int R = g_parp[pbase + (int)lr];       // 1 hop: flattened
            if (g_smax[R] > g_smin[R]) w = 11.0f;  // merged component
        }
        s += (double)(pl * w);
    }

    sh[threadIdx.x] = s;
    __syncthreads();
    for (int off = 128; off > 0; off >>= 1) {
        if (threadIdx.x < off) sh[threadIdx.x] += sh[threadIdx.x + off];
        __syncthreads();
    }
    __shared__ bool last;
    if (threadIdx.x == 0) {
        g_psum[blockIdx.x] = sh[0];
        __threadfence();
        last = (atomicAdd(&g_ctr, 1) == (int)gridDim.x - 1);
    }
    __syncthreads();

    if (last) {
        double s2 = 0.0;
        for (int k = 0; k < LOSS_BLOCKS / 256; k++)          // fixed order
            s2 += g_psum[threadIdx.x + 256 * k];
        sh[threadIdx.x] = s2;
        __syncthreads();
        for (int off = 128; off > 0; off >>= 1) {
            if (threadIdx.x < off) sh[threadIdx.x] += sh[threadIdx.x + off];
            __syncthreads();
        }
        if (threadIdx.x == 0) {
            out[0] = (float)(sh[0] / (double)NTOT);
            g_ctr = 0;                                       // reset for replay
        }
    }
}

// ---------------------------------------------------------------------------
extern "C" void kernel_launch(void* const* d_in, const int* in_sizes, int n_in,
                              void* d_out, int out_size) {
    const float* pred   = (const float*)d_in[0];
    const float* target = (const float*)d_in[1];
    float* out = (float*)d_out;

    k_flag<<<N4 / 256, 256>>>((const float4*)pred);
    k_tile<<<dim3(TILES_X, TILES_Y, BB), dim3(TS, TS)>>>(pred, target);
    k_bmerge<<<(NEDGE + 255) / 256, 256>>>();
    k_compress<<<COMP_BLOCKS, 256>>>();
    k_agg<<<NTOT / 256, 256>>>();
    k_loss<<<LOSS_BLOCKS, 256>>>((const float4*)pred, (const float4*)target, out);
}

// round 13
// speedup vs baseline: 1.4177x; 1.0363x over previous
#include <cuda_runtime.h>
#include <climits>

// Fixed problem shape: B=8, C=1, H=W=768.
#define BB    8
#define HH    768
#define WW    768
#define HWSZ  (HH * WW)          // 589824
#define NTOT  (BB * HWSZ)        // 4718592
#define N4    (NTOT / 4)         // 1179648

#define TS        32
#define TILES_X   24
#define TILES_Y   24
#define NTILES    (BB * TILES_X * TILES_Y)   // 4608

#define EPT   (23 * 768)
#define EPI   (2 * EPT)          // 35328
#define NEDGE (BB * EPI)         // 282624

#define BG16  0xFFFFu
#define MAXR  (NTOT / 2)         // hard cap on roots per mask
#define LOSS_BLOCKS (N4 / 256)   // 4608
#define COMP_BLOCKS 1024
#define FLAG_BLOCKS 2048

// Scratch (static __device__ arrays; allocation-free kernel_launch).
__device__ unsigned short g_locp[NTOT];  // per-pixel pred tile-root rank (BG16 = bg)
__device__ unsigned short g_loct[NTOT];  // per-pixel target tile-root rank
__device__ int      g_pbase[NTILES];  // compact-ID base per tile (pred)
__device__ int      g_tbase[NTILES];  // compact-ID base per tile (target)
__device__ int      g_parp[MAXR];     // pred UF parents over compact IDs (L2-resident)
__device__ int      g_part[MAXR];     // target UF parents over compact IDs
__device__ int      g_smin[MAXR];     // min target ID per pred root
__device__ int      g_smax[MAXR];     // max target ID per pred root
__device__ int      g_np, g_nt;       // compact-ID counters (reset by k_flag)
__device__ int      g_flag;           // rescale flag (published fresh each run)
__device__ int      g_neg, g_ctrf;    // k_flag state (zero-init, self-reset)
__device__ int      g_ctr;            // k_loss last-block counter (self-reset)
__device__ double   g_psum[LOSS_BLOCKS];

// Exact reference arithmetic for (x + 1.0) * 0.5 without FMA contraction.
__device__ __forceinline__ float resc01(float x) {
    return __fmul_rn(__fadd_rn(x, 1.0f), 0.5f);
}

// ---------------------------------------------------------------------------
// Union-find over compact IDs (min-ID rooting; parent <= child invariant)
// ---------------------------------------------------------------------------
__device__ __forceinline__ int uf_find(const int* L, int x) {
    int p = L[x];
    while (p != x) { x = p; p = L[x]; }
    return x;
}

__device__ __forceinline__ int uf_findc(int* L, int x) {   // find + compress
    int r = x, p = L[r];
    while (p != r) { r = p; p = L[r]; }
    while (L[x] != r) { int nx = L[x]; L[x] = r; x = nx; }
    return r;
}

__device__ __forceinline__ void uf_union(int* L, int a, int b) {
    int ra = uf_find(L, a);
    int rb = uf_find(L, b);
    while (ra != rb) {
        int hi = ra > rb ? ra : rb;
        int lo = ra > rb ? rb : ra;
        int old = atomicMin(&L[hi], lo);
        if (old == hi) break;
        ra = lo;
        rb = old;
    }
}

// Shared-memory union-find (tile-local labels).
__device__ __forceinline__ int s_find(const int* L, int x) {
    int p = L[x];
    while (p != x) { x = p; p = L[x]; }
    return x;
}

__device__ __forceinline__ void s_union(int* L, int a, int b) {
    int ra = s_find(L, a);
    int rb = s_find(L, b);
    while (ra != rb) {
        int hi = ra > rb ? ra : rb;
        int lo = ra > rb ? rb : ra;
        int old = atomicMin(&L[hi], lo);
        if (old == hi) break;
        ra = lo;
        rb = old;
    }
}

// ---------------------------------------------------------------------------
// Kernels
// ---------------------------------------------------------------------------
// Publish rescale flag fresh each run; reset compact-ID counters before k_tile.
__global__ void k_flag(const float4* __restrict__ pred) {
    bool neg = false;
    for (int i = blockIdx.x * blockDim.x + threadIdx.x; i < N4;
         i += FLAG_BLOCKS * 256) {
        float4 v = pred[i];
        neg |= (v.x < 0.f) | (v.y < 0.f) | (v.z < 0.f) | (v.w < 0.f);
    }
    bool bneg = __syncthreads_or(neg);
    __shared__ bool last;
    if (threadIdx.x == 0) {
        if (bneg) atomicOr(&g_neg, 1);
        __threadfence();
        last = (atomicAdd(&g_ctrf, 1) == (int)gridDim.x - 1);
    }
    __syncthreads();
    if (last && threadIdx.x == 0) {
        g_flag = g_neg; g_neg = 0; g_ctrf = 0;
        g_np = 0; g_nt = 0;
    }
}

// Per 32x32 tile: masks, in-tile CCL, compact-ID assignment (ballot prefix +
// one global atomicAdd per mask), u16 rank labels, compact UF/minmax init.
__global__ void k_tile(const float* __restrict__ pred,
                       const float* __restrict__ target) {
    __shared__ int lp[TS * TS];
    __shared__ int lt[TS * TS];
    __shared__ int sWp[32], sWt[32];
    __shared__ int s_pb, s_tb;

    int lx = threadIdx.x, ly = threadIdx.y;
    int l  = ly * TS + lx;
    int b  = blockIdx.z;
    int gi = b * HWSZ + (blockIdx.y * TS + ly) * WW + blockIdx.x * TS + lx;
    int tileIdx = (b * TILES_Y + blockIdx.y) * TILES_X + blockIdx.x;

    bool  resc = (g_flag != 0);
    float p = pred[gi];
    float t = target[gi];
    float pp  = resc ? resc01(p) : p;
    float t01 = resc01(t);
    bool mp = pp  > 0.5f;
    bool mt = t01 > 0.5f;

    lp[l] = mp ? l : -1;
    lt[l] = mt ? l : -1;
    __syncthreads();

    if (mp) {
        if (lx > 0 && lp[l - 1]  >= 0) s_union(lp, l, l - 1);
        if (ly > 0 && lp[l - TS] >= 0) s_union(lp, l, l - TS);
    }
    if (mt) {
        if (lx > 0 && lt[l - 1]  >= 0) s_union(lt, l, l - 1);
        if (ly > 0 && lt[l - TS] >= 0) s_union(lt, l, l - TS);
    }
    __syncthreads();

    int rp = mp ? s_find(lp, l) : -1;
    int rt = mt ? s_find(lt, l) : -1;
    bool rootp = mp && (rp == l);
    bool roott = mt && (rt == l);

    unsigned balp = __ballot_sync(0xffffffffu, rootp);
    unsigned balt = __ballot_sync(0xffffffffu, roott);
    if (lx == 0) { sWp[ly] = __popc(balp); sWt[ly] = __popc(balt); }
    __syncthreads();

    // Exclusive scan of per-warp root counts; warp 0 = pred, warp 1 = target.
    if (l < 32) {
        int orig = sWp[l], v = orig;
        #pragma unroll
        for (int o = 1; o < 32; o <<= 1) {
            int n = __shfl_up_sync(0xffffffffu, v, o);
            if (l >= o) v += n;
        }
        sWp[l] = v - orig;
        if (l == 31) s_pb = atomicAdd(&g_np, v);
    } else if (l < 64) {
        int k = l - 32;
        int orig = sWt[k], v = orig;
        #pragma unroll
        for (int o = 1; o < 32; o <<= 1) {
            int n = __shfl_up_sync(0xffffffffu, v, o);
            if (k >= o) v += n;
        }
        sWt[k] = v - orig;
        if (k == 31) s_tb = atomicAdd(&g_nt, v);
    }
    __syncthreads();

    // Roots: compute rank, init compact entries, publish rank via lp/lt[l].
    unsigned lmask = (1u << lx) - 1u;
    if (rootp) {
        int rank = sWp[ly] + __popc(balp & lmask);
        int cid  = s_pb + rank;
        lp[l] = rank;
        g_parp[cid] = cid;
        g_smin[cid] = INT_MAX;
        g_smax[cid] = -1;
    }
    if (roott) {
        int rank = sWt[ly] + __popc(balt & lmask);
        lt[l] = rank;
        g_part[s_tb + rank] = s_tb + rank;
    }
    __syncthreads();

    g_locp[gi] = mp ? (unsigned short)lp[rp] : (unsigned short)BG16;
    g_loct[gi] = mt ? (unsigned short)lt[rt] : (unsigned short)BG16;
    if (l == 0) { g_pbase[tileIdx] = s_pb; g_tbase[tileIdx] = s_tb; }
}

// Merge across tile boundaries; one thread = one edge, both masks.
// All UF traffic hits the compact (L2-resident) arrays.
__global__ void k_bmerge() {
    int tid = blockIdx.x * blockDim.x + threadIdx.x;
    if (tid >= NEDGE) return;
    int b = tid / EPI;
    int e = tid % EPI;
    int y, x, ny, nx;
    if (e < EPT) {                       // vertical boundary: (y,x)-(y,x-1)
        int bi = e / HH; y = e % HH;
        x = TS * (bi + 1); ny = y; nx = x - 1;
    } else {                             // horizontal boundary: (y,x)-(y-1,x)
        e -= EPT;
        int bi = e / WW; x = e % WW;
        y = TS * (bi + 1); ny = y - 1; nx = x;
    }
    int idx = b * HWSZ + y * WW + x;
    int n   = b * HWSZ + ny * WW + nx;
    unsigned ap = g_locp[idx], cp = g_locp[n];
    unsigned at = g_loct[idx], ct = g_loct[n];
    int tA = (b * TILES_Y + (y  >> 5)) * TILES_X + (x  >> 5);
    int tC = (b * TILES_Y + (ny >> 5)) * TILES_X + (nx >> 5);

    if (ap != BG16 && cp != BG16)
        uf_union(g_parp, g_pbase[tA] + (int)ap, g_pbase[tC] + (int)cp);
    if (at != BG16 && ct != BG16)
        uf_union(g_part, g_tbase[tA] + (int)at, g_tbase[tC] + (int)ct);
}

// Flatten EVERY live compact entry to its final root. Live sets are exactly
// [0, g_np) and [0, g_nt). One independent short chase per thread (high MLP).
__global__ void k_compress() {
    int np = g_np, nt = g_nt;
    int total = np + nt;
    for (int i = blockIdx.x * blockDim.x + threadIdx.x; i < total;
         i += gridDim.x * blockDim.x) {
        if (i < np) uf_findc(g_parp, i);
        else        uf_findc(g_part, i - np);
    }
}

// 4 pixels/thread: independent 1-hop root loads feed L2-resident min/max
// atomics; identical adjacent pairs deduped before the atomic.
__global__ void k_agg() {
    int v = blockIdx.x * blockDim.x + threadIdx.x;   // exact cover of N4
    ushort4 P = ((const ushort4*)g_locp)[v];
    ushort4 T = ((const ushort4*)g_loct)[v];
    unsigned pv[4] = {P.x, P.y, P.z, P.w};
    unsigned tv[4] = {T.x, T.y, T.z, T.w};

    int i0  = 4 * v;
    int b   = i0 / HWSZ;
    int rem = i0 - b * HWSZ;
    int tile = (b * TILES_Y + ((rem / WW) >> 5)) * TILES_X + ((rem % WW) >> 5);
    int pb = g_pbase[tile], tb = g_tbase[tile];   // all 4 px share one tile

    int prev_rp = -1, prev_rt = -1;
    #pragma unroll
    for (int j = 0; j < 4; j++) {
        if (pv[j] == BG16 || tv[j] == BG16) continue;
        int rp = g_parp[pb + (int)pv[j]];   // 1 hop: flattened
        int rt = g_part[tb + (int)tv[j]];
        if (rp == prev_rp && rt == prev_rt) continue;   // dedup adjacent
        prev_rp = rp; prev_rt = rt;
        atomicMin(&g_smin[rp], rt);
        atomicMax(&g_smax[rp], rt);
    }
}

// Weighted loss + fused deterministic final reduction (last-block pattern).
__global__ void k_loss(const float4* __restrict__ pred,
                       const float4* __restrict__ target,
                       float* __restrict__ out) {
    __shared__ double sh[256];
    bool resc = (g_flag != 0);
    int v = blockIdx.x * blockDim.x + threadIdx.x;   // exact cover of N4
    int i0  = 4 * v;
    int b   = i0 / HWSZ;
    int rem = i0 - b * HWSZ;
    int tile = (b * TILES_Y + ((rem / WW) >> 5)) * TILES_X + ((rem % WW) >> 5);
    int pbase = g_pbase[tile];   // all 4 pixels share one tile (x0 % 4 == 0)

    float4 p = pred[v];
    float4 t = target[v];
    ushort4 L = ((const ushort4*)g_locp)[v];
    float pv[4] = {p.x, p.y, p.z, p.w};
    float tv[4] = {t.x, t.y, t.z, t.w};
    unsigned lv[4] = {L.x, L.y, L.z, L.w};

    double s = 0.0;
    #pragma unroll
    for (int j = 0; j < 4; j++) {
        float pp  = resc ? resc01(pv[j]) : pv[j];
        float t01 = resc01(tv[j]);
        float pl  = fabsf(pp - t01);
        float w   = 1.0f;
        if (lv[j] != BG16 && !(t01 > 0.5f)) {      // pred fg, target bg
            int R = g_parp[pbase + (int)lv[j]];     // 1 hop: flattened
            if (g_smax[R] > g_smin[R]) w = 11.0f;   // merged component
        }
        s += (double)(pl * w);
    }

    sh[threadIdx.x] = s;
    __syncthreads();
    for (int off = 128; off > 0; off >>= 1) {
        if (threadIdx.x < off) sh[threadIdx.x] += sh[threadIdx.x + off];
        __syncthreads();
    }
    __shared__ bool last;
    if (threadIdx.x == 0) {
        g_psum[blockIdx.x] = sh[0];
        __threadfence();
        last = (atomicAdd(&g_ctr, 1) == (int)gridDim.x - 1);
    }
    __syncthreads();

    if (last) {
        double s2 = 0.0;
        for (int k = 0; k < LOSS_BLOCKS / 256; k++)          // fixed order
            s2 += g_psum[threadIdx.x + 256 * k];
        sh[threadIdx.x] = s2;
        __syncthreads();
        for (int off = 128; off > 0; off >>= 1) {
            if (threadIdx.x < off) sh[threadIdx.x] += sh[threadIdx.x + off];
            __syncthreads();
        }
        if (threadIdx.x == 0) {
            out[0] = (float)(sh[0] / (double)NTOT);
            g_ctr = 0;                                       // reset for replay
        }
    }
}

// ---------------------------------------------------------------------------
extern "C" void kernel_launch(void* const* d_in, const int* in_sizes, int n_in,
                              void* d_out, int out_size) {
    const float* pred   = (const float*)d_in[0];
    const float* target = (const float*)d_in[1];
    float* out = (float*)d_out;

    k_flag<<<FLAG_BLOCKS, 256>>>((const float4*)pred);
    k_tile<<<dim3(TILES_X, TILES_Y, BB), dim3(TS, TS)>>>(pred, target);
    k_bmerge<<<(NEDGE + 255) / 256, 256>>>();
    k_compress<<<COMP_BLOCKS, 256>>>();
    k_agg<<<N4 / 256, 256>>>();
    k_loss<<<LOSS_BLOCKS, 256>>>((const float4*)pred, (const float4*)target, out);
}

// round 14
// speedup vs baseline: 1.6497x; 1.1636x over previous
#include <cuda_runtime.h>
#include <climits>

// Fixed problem shape: B=8, C=1, H=W=768.
#define BB    8
#define HH    768
#define WW    768
#define HWSZ  (HH * WW)          // 589824
#define NTOT  (BB * HWSZ)        // 4718592
#define N4    (NTOT / 4)         // 1179648

#define TS        32
#define TILES_X   24
#define TILES_Y   24
#define NTILES    (BB * TILES_X * TILES_Y)   // 4608

#define EPT   (23 * 768)
#define EPI   (2 * EPT)          // 35328
#define NEDGE (BB * EPI)         // 282624

#define BG16  0xFFFFu
#define MAXR  (NTOT / 2)         // hard cap on roots per mask
#define LOSS_BLOCKS (N4 / 256)   // 4608
#define COMP_BLOCKS 1024
#define FLAG_BLOCKS 2048
#define MARK_BLOCKS 512

// Scratch (static __device__ arrays; allocation-free kernel_launch).
__device__ unsigned short g_locp[NTOT];  // per-pixel pred tile-root rank (BG16 = bg)
__device__ unsigned short g_loct[NTOT];  // per-pixel target tile-root rank
__device__ int      g_pbase[NTILES];  // compact-ID base per tile (pred)
__device__ int      g_tbase[NTILES];  // compact-ID base per tile (target)
__device__ int      g_parp[MAXR];     // pred UF parents over compact IDs (L2-resident)
__device__ int      g_part[MAXR];     // target UF parents over compact IDs
__device__ int      g_smin[MAXR];     // min target ID per pred root
__device__ int      g_smax[MAXR];     // max target ID per pred root
__device__ unsigned char g_merged[MAXR]; // per pred compact ID: merged-component flag
__device__ int      g_np, g_nt;       // compact-ID counters (reset by k_flag)
__device__ int      g_flag;           // rescale flag (published fresh each run)
__device__ int      g_neg, g_ctrf;    // k_flag state (zero-init, self-reset)
__device__ int      g_ctr;            // k_loss last-block counter (self-reset)
__device__ double   g_psum[LOSS_BLOCKS];

// Exact reference arithmetic for (x + 1.0) * 0.5 without FMA contraction.
__device__ __forceinline__ float resc01(float x) {
    return __fmul_rn(__fadd_rn(x, 1.0f), 0.5f);
}

// ---------------------------------------------------------------------------
// Union-find over compact IDs (min-ID rooting; parent <= child invariant)
// ---------------------------------------------------------------------------
__device__ __forceinline__ int uf_find(const int* L, int x) {
    int p = L[x];
    while (p != x) { x = p; p = L[x]; }
    return x;
}

__device__ __forceinline__ int uf_findc(int* L, int x) {   // find + compress
    int r = x, p = L[r];
    while (p != r) { r = p; p = L[r]; }
    while (L[x] != r) { int nx = L[x]; L[x] = r; x = nx; }
    return r;
}

__device__ __forceinline__ void uf_union(int* L, int a, int b) {
    int ra = uf_find(L, a);
    int rb = uf_find(L, b);
    while (ra != rb) {
        int hi = ra > rb ? ra : rb;
        int lo = ra > rb ? rb : ra;
        int old = atomicMin(&L[hi], lo);
        if (old == hi) break;
        ra = lo;
        rb = old;
    }
}

// Shared-memory union-find (tile-local labels).
__device__ __forceinline__ int s_find(const int* L, int x) {
    int p = L[x];
    while (p != x) { x = p; p = L[x]; }
    return x;
}

__device__ __forceinline__ void s_union(int* L, int a, int b) {
    int ra = s_find(L, a);
    int rb = s_find(L, b);
    while (ra != rb) {
        int hi = ra > rb ? ra : rb;
        int lo = ra > rb ? rb : ra;
        int old = atomicMin(&L[hi], lo);
        if (old == hi) break;
        ra = lo;
        rb = old;
    }
}

// ---------------------------------------------------------------------------
// Kernels
// ---------------------------------------------------------------------------
// Publish rescale flag fresh each run; reset compact-ID counters before k_tile.
__global__ void k_flag(const float4* __restrict__ pred) {
    bool neg = false;
    for (int i = blockIdx.x * blockDim.x + threadIdx.x; i < N4;
         i += FLAG_BLOCKS * 256) {
        float4 v = pred[i];
        neg |= (v.x < 0.f) | (v.y < 0.f) | (v.z < 0.f) | (v.w < 0.f);
    }
    bool bneg = __syncthreads_or(neg);
    __shared__ bool last;
    if (threadIdx.x == 0) {
        if (bneg) atomicOr(&g_neg, 1);
        __threadfence();
        last = (atomicAdd(&g_ctrf, 1) == (int)gridDim.x - 1);
    }
    __syncthreads();
    if (last && threadIdx.x == 0) {
        g_flag = g_neg; g_neg = 0; g_ctrf = 0;
        g_np = 0; g_nt = 0;
    }
}

// Per 32x32 tile: masks, row-run labels via ballot (horizontal connectivity is
// free), vertical unions only, compact-ID assignment, u16 rank labels.
__global__ void k_tile(const float* __restrict__ pred,
                       const float* __restrict__ target) {
    __shared__ int lp[TS * TS];
    __shared__ int lt[TS * TS];
    __shared__ int sWp[32], sWt[32];
    __shared__ int s_pb, s_tb;

    int lx = threadIdx.x, ly = threadIdx.y;
    int l  = ly * TS + lx;
    int b  = blockIdx.z;
    int gi = b * HWSZ + (blockIdx.y * TS + ly) * WW + blockIdx.x * TS + lx;
    int tileIdx = (b * TILES_Y + blockIdx.y) * TILES_X + blockIdx.x;

    bool  resc = (g_flag != 0);
    float p = pred[gi];
    float t = target[gi];
    float pp  = resc ? resc01(p) : p;
    float t01 = resc01(t);
    bool mp = pp  > 0.5f;
    bool mt = t01 > 0.5f;

    // Row-run labeling: label = index of my run's start lane (<= my lane).
    unsigned mle = 0xffffffffu >> (31 - lx);      // lanes <= me
    unsigned bp  = __ballot_sync(0xffffffffu, mp);
    unsigned bt  = __ballot_sync(0xffffffffu, mt);
    unsigned stp = bp & ~(bp << 1);               // run-start lanes
    unsigned stt = bt & ~(bt << 1);
    lp[l] = mp ? ly * TS + (31 - __clz(stp & mle)) : -1;
    lt[l] = mt ? ly * TS + (31 - __clz(stt & mle)) : -1;
    __syncthreads();

    // Vertical unions only (horizontal handled by run labels).
    if (ly > 0) {
        if (mp && lp[l - TS] >= 0) s_union(lp, l, l - TS);
        if (mt && lt[l - TS] >= 0) s_union(lt, l, l - TS);
    }
    __syncthreads();

    int rp = mp ? s_find(lp, l) : -1;
    int rt = mt ? s_find(lt, l) : -1;
    bool rootp = mp && (rp == l);
    bool roott = mt && (rt == l);

    unsigned balp = __ballot_sync(0xffffffffu, rootp);
    unsigned balt = __ballot_sync(0xffffffffu, roott);
    if (lx == 0) { sWp[ly] = __popc(balp); sWt[ly] = __popc(balt); }
    __syncthreads();

    // Exclusive scan of per-warp root counts; warp 0 = pred, warp 1 = target.
    if (l < 32) {
        int orig = sWp[l], v = orig;
        #pragma unroll
        for (int o = 1; o < 32; o <<= 1) {
            int n = __shfl_up_sync(0xffffffffu, v, o);
            if (l >= o) v += n;
        }
        sWp[l] = v - orig;
        if (l == 31) s_pb = atomicAdd(&g_np, v);
    } else if (l < 64) {
        int k = l - 32;
        int orig = sWt[k], v = orig;
        #pragma unroll
        for (int o = 1; o < 32; o <<= 1) {
            int n = __shfl_up_sync(0xffffffffu, v, o);
            if (k >= o) v += n;
        }
        sWt[k] = v - orig;
        if (k == 31) s_tb = atomicAdd(&g_nt, v);
    }
    __syncthreads();

    // Roots: compute rank, init compact entries, publish rank via lp/lt[l].
    unsigned lmask = (1u << lx) - 1u;
    if (rootp) {
        int rank = sWp[ly] + __popc(balp & lmask);
        int cid  = s_pb + rank;
        lp[l] = rank;
        g_parp[cid] = cid;
        g_smin[cid] = INT_MAX;
        g_smax[cid] = -1;
    }
    if (roott) {
        int rank = sWt[ly] + __popc(balt & lmask);
        lt[l] = rank;
        g_part[s_tb + rank] = s_tb + rank;
    }
    __syncthreads();

    g_locp[gi] = mp ? (unsigned short)lp[rp] : (unsigned short)BG16;
    g_loct[gi] = mt ? (unsigned short)lt[rt] : (unsigned short)BG16;
    if (l == 0) { g_pbase[tileIdx] = s_pb; g_tbase[tileIdx] = s_tb; }
}

// Merge across tile boundaries; one thread = one edge, both masks.
__global__ void k_bmerge() {
    int tid = blockIdx.x * blockDim.x + threadIdx.x;
    if (tid >= NEDGE) return;
    int b = tid / EPI;
    int e = tid % EPI;
    int y, x, ny, nx;
    if (e < EPT) {                       // vertical boundary: (y,x)-(y,x-1)
        int bi = e / HH; y = e % HH;
        x = TS * (bi + 1); ny = y; nx = x - 1;
    } else {                             // horizontal boundary: (y,x)-(y-1,x)
        e -= EPT;
        int bi = e / WW; x = e % WW;
        y = TS * (bi + 1); ny = y - 1; nx = x;
    }
    int idx = b * HWSZ + y * WW + x;
    int n   = b * HWSZ + ny * WW + nx;
    unsigned ap = g_locp[idx], cp = g_locp[n];
    unsigned at = g_loct[idx], ct = g_loct[n];
    int tA = (b * TILES_Y + (y  >> 5)) * TILES_X + (x  >> 5);
    int tC = (b * TILES_Y + (ny >> 5)) * TILES_X + (nx >> 5);

    if (ap != BG16 && cp != BG16)
        uf_union(g_parp, g_pbase[tA] + (int)ap, g_pbase[tC] + (int)cp);
    if (at != BG16 && ct != BG16)
        uf_union(g_part, g_tbase[tA] + (int)at, g_tbase[tC] + (int)ct);
}

// Flatten EVERY live compact entry to its final root. Live sets are exactly
// [0, g_np) and [0, g_nt). One independent short chase per thread (high MLP).
__global__ void k_compress() {
    int np = g_np, nt = g_nt;
    int total = np + nt;
    for (int i = blockIdx.x * blockDim.x + threadIdx.x; i < total;
         i += gridDim.x * blockDim.x) {
        if (i < np) uf_findc(g_parp, i);
        else        uf_findc(g_part, i - np);
    }
}

// 4 pixels/thread: independent 1-hop root loads feed L2-resident min/max
// atomics; identical adjacent pairs deduped before the atomic.
__global__ void k_agg() {
    int v = blockIdx.x * blockDim.x + threadIdx.x;   // exact cover of N4
    ushort4 P = ((const ushort4*)g_locp)[v];
    ushort4 T = ((const ushort4*)g_loct)[v];
    unsigned pv[4] = {P.x, P.y, P.z, P.w};
    unsigned tv[4] = {T.x, T.y, T.z, T.w};

    int i0  = 4 * v;
    int b   = i0 / HWSZ;
    int rem = i0 - b * HWSZ;
    int tile = (b * TILES_Y + ((rem / WW) >> 5)) * TILES_X + ((rem % WW) >> 5);
    int pb = g_pbase[tile], tb = g_tbase[tile];   // all 4 px share one tile

    int prev_rp = -1, prev_rt = -1;
    #pragma unroll
    for (int j = 0; j < 4; j++) {
        if (pv[j] == BG16 || tv[j] == BG16) continue;
        int rp = g_parp[pb + (int)pv[j]];   // 1 hop: flattened
        int rt = g_part[tb + (int)tv[j]];
        if (rp == prev_rp && rt == prev_rt) continue;   // dedup adjacent
        prev_rp = rp; prev_rt = rt;
        atomicMin(&g_smin[rp], rt);
        atomicMax(&g_smax[rp], rt);
    }
}

// Per pred compact ID: resolve merged flag once (L2-resident; ~2us) so that
// k_loss needs only a single independent byte load per candidate pixel.
__global__ void k_mark() {
    int np = g_np;
    for (int i = blockIdx.x * blockDim.x + threadIdx.x; i < np;
         i += gridDim.x * blockDim.x) {
        int r = g_parp[i];               // final root (flattened)
        g_merged[i] = (g_smax[r] > g_smin[r]) ? 1 : 0;
    }
}

// Weighted loss + fused deterministic final reduction (last-block pattern).
__global__ void k_loss(const float4* __restrict__ pred,
                       const float4* __restrict__ target,
                       float* __restrict__ out) {
    __shared__ double sh[256];
    bool resc = (g_flag != 0);
    int v = blockIdx.x * blockDim.x + threadIdx.x;   // exact cover of N4
    int i0  = 4 * v;
    int b   = i0 / HWSZ;
    int rem = i0 - b * HWSZ;
    int tile = (b * TILES_Y + ((rem / WW) >> 5)) * TILES_X + ((rem % WW) >> 5);
    int pbase = g_pbase[tile];   // all 4 pixels share one tile (x0 % 4 == 0)

    float4 p = pred[v];
    float4 t = target[v];
    ushort4 L = ((const ushort4*)g_locp)[v];
    float pv[4] = {p.x, p.y, p.z, p.w};
    float tv[4] = {t.x, t.y, t.z, t.w};
    unsigned lv[4] = {L.x, L.y, L.z, L.w};

    double s = 0.0;
    #pragma unroll
    for (int j = 0; j < 4; j++) {
        float pp  = resc ? resc01(pv[j]) : pv[j];
        float t01 = resc01(tv[j]);
        float pl  = fabsf(pp - t01);
        float w   = 1.0f;
        if (lv[j] != BG16 && !(t01 > 0.5f)) {      // pred fg, target bg
            if (g_merged[pbase + (int)lv[j]]) w = 11.0f;   // single byte load
        }
        s += (double)(pl * w);
    }

    sh[threadIdx.x] = s;
    __syncthreads();
    for (int off = 128; off > 0; off >>= 1) {
        if (threadIdx.x < off) sh[threadIdx.x] += sh[threadIdx.x + off];
        __syncthreads();
    }
    __shared__ bool last;
    if (threadIdx.x == 0) {
        g_psum[blockIdx.x] = sh[0];
        __threadfence();
        last = (atomicAdd(&g_ctr, 1) == (int)gridDim.x - 1);
    }
    __syncthreads();

    if (last) {
        double s2 = 0.0;
        for (int k = 0; k < LOSS_BLOCKS / 256; k++)          // fixed order
            s2 += g_psum[threadIdx.x + 256 * k];
        sh[threadIdx.x] = s2;
        __syncthreads();
        for (int off = 128; off > 0; off >>= 1) {
            if (threadIdx.x < off) sh[threadIdx.x] += sh[threadIdx.x + off];
            __syncthreads();
        }
        if (threadIdx.x == 0) {
            out[0] = (float)(sh[0] / (double)NTOT);
            g_ctr = 0;                                       // reset for replay
        }
    }
}

// ---------------------------------------------------------------------------
extern "C" void kernel_launch(void* const* d_in, const int* in_sizes, int n_in,
                              void* d_out, int out_size) {
    const float* pred   = (const float*)d_in[0];
    const float* target = (const float*)d_in[1];
    float* out = (float*)d_out;

    k_flag<<<FLAG_BLOCKS, 256>>>((const float4*)pred);
    k_tile<<<dim3(TILES_X, TILES_Y, BB), dim3(TS, TS)>>>(pred, target);
    k_bmerge<<<(NEDGE + 255) / 256, 256>>>();
    k_compress<<<COMP_BLOCKS, 256>>>();
    k_agg<<<N4 / 256, 256>>>();
    k_mark<<<MARK_BLOCKS, 256>>>();
    k_loss<<<LOSS_BLOCKS, 256>>>((const float4*)pred, (const float4*)target, out);
}

// round 15
// speedup vs baseline: 1.6744x; 1.0150x over previous
#include <cuda_runtime.h>
#include <cuda_fp16.h>
#include <climits>

// Fixed problem shape: B=8, C=1, H=W=768.
#define BB    8
#define HH    768
#define WW    768
#define HWSZ  (HH * WW)          // 589824
#define NTOT  (BB * HWSZ)        // 4718592
#define N4    (NTOT / 4)         // 1179648
#define N8    (NTOT / 8)         // 589824

#define TS        32
#define TILES_X   24
#define TILES_Y   24
#define NTILES    (BB * TILES_X * TILES_Y)   // 4608

#define EPT   (23 * 768)
#define EPI   (2 * EPT)          // 35328
#define NEDGE (BB * EPI)         // 282624

#define BG16  0xFFFFu
#define MAXR  (NTOT / 2)         // hard cap on roots per mask
#define LOSS_BLOCKS (N8 / 256)   // 2304
#define COMP_BLOCKS 1024
#define FLAG_BLOCKS 2048
#define MARK_BLOCKS 512

// Scratch (static __device__ arrays; allocation-free kernel_launch).
__device__ unsigned short g_locp[NTOT];  // per-pixel pred tile-root rank (BG16 = bg)
__device__ unsigned short g_loct[NTOT];  // per-pixel target tile-root rank
__device__ unsigned short g_plh[NTOT];   // fp16 |pl| ; sign bit = target-fg mask
__device__ int      g_pbase[NTILES];  // compact-ID base per tile (pred)
__device__ int      g_tbase[NTILES];  // compact-ID base per tile (target)
__device__ int      g_parp[MAXR];     // pred UF parents over compact IDs (L2-resident)
__device__ int      g_part[MAXR];     // target UF parents over compact IDs
__device__ int      g_smin[MAXR];     // min target ID per pred root
__device__ int      g_smax[MAXR];     // max target ID per pred root
__device__ unsigned char g_merged[MAXR]; // per pred compact ID: merged-component flag
__device__ int      g_np, g_nt;       // compact-ID counters (reset by k_flag)
__device__ int      g_flag;           // rescale flag (published fresh each run)
__device__ int      g_neg, g_ctrf;    // k_flag state (zero-init, self-reset)
__device__ int      g_ctr;            // k_loss last-block counter (self-reset)
__device__ double   g_psum[LOSS_BLOCKS];

// Exact reference arithmetic for (x + 1.0) * 0.5 without FMA contraction.
__device__ __forceinline__ float resc01(float x) {
    return __fmul_rn(__fadd_rn(x, 1.0f), 0.5f);
}

// ---------------------------------------------------------------------------
// Union-find over compact IDs (min-ID rooting; parent <= child invariant)
// ---------------------------------------------------------------------------
__device__ __forceinline__ int uf_find(const int* L, int x) {
    int p = L[x];
    while (p != x) { x = p; p = L[x]; }
    return x;
}

__device__ __forceinline__ int uf_findc(int* L, int x) {   // find + compress
    int r = x, p = L[r];
    while (p != r) { r = p; p = L[r]; }
    while (L[x] != r) { int nx = L[x]; L[x] = r; x = nx; }
    return r;
}

__device__ __forceinline__ void uf_union(int* L, int a, int b) {
    int ra = uf_find(L, a);
    int rb = uf_find(L, b);
    while (ra != rb) {
        int hi = ra > rb ? ra : rb;
        int lo = ra > rb ? rb : ra;
        int old = atomicMin(&L[hi], lo);
        if (old == hi) break;
        ra = lo;
        rb = old;
    }
}

// Shared-memory union-find (tile-local labels).
__device__ __forceinline__ int s_find(const int* L, int x) {
    int p = L[x];
    while (p != x) { x = p; p = L[x]; }
    return x;
}

__device__ __forceinline__ void s_union(int* L, int a, int b) {
    int ra = s_find(L, a);
    int rb = s_find(L, b);
    while (ra != rb) {
        int hi = ra > rb ? ra : rb;
        int lo = ra > rb ? rb : ra;
        int old = atomicMin(&L[hi], lo);
        if (old == hi) break;
        ra = lo;
        rb = old;
    }
}

// ---------------------------------------------------------------------------
// Kernels
// ---------------------------------------------------------------------------
// Publish rescale flag fresh each run; reset compact-ID counters before k_tile.
__global__ void k_flag(const float4* __restrict__ pred) {
    bool neg = false;
    for (int i = blockIdx.x * blockDim.x + threadIdx.x; i < N4;
         i += FLAG_BLOCKS * 256) {
        float4 v = pred[i];
        neg |= (v.x < 0.f) | (v.y < 0.f) | (v.z < 0.f) | (v.w < 0.f);
    }
    bool bneg = __syncthreads_or(neg);
    __shared__ bool last;
    if (threadIdx.x == 0) {
        if (bneg) atomicOr(&g_neg, 1);
        __threadfence();
        last = (atomicAdd(&g_ctrf, 1) == (int)gridDim.x - 1);
    }
    __syncthreads();
    if (last && threadIdx.x == 0) {
        g_flag = g_neg; g_neg = 0; g_ctrf = 0;
        g_np = 0; g_nt = 0;
    }
}

// Per 32x32 tile: masks, row-run labels via ballot, vertical unions only,
// compact-ID assignment, u16 rank labels, fp16 pixel-loss store.
__global__ void k_tile(const float* __restrict__ pred,
                       const float* __restrict__ target) {
    __shared__ int lp[TS * TS];
    __shared__ int lt[TS * TS];
    __shared__ int sWp[32], sWt[32];
    __shared__ int s_pb, s_tb;

    int lx = threadIdx.x, ly = threadIdx.y;
    int l  = ly * TS + lx;
    int b  = blockIdx.z;
    int gi = b * HWSZ + (blockIdx.y * TS + ly) * WW + blockIdx.x * TS + lx;
    int tileIdx = (b * TILES_Y + blockIdx.y) * TILES_X + blockIdx.x;

    bool  resc = (g_flag != 0);
    float p = pred[gi];
    float t = target[gi];
    float pp  = resc ? resc01(p) : p;
    float t01 = resc01(t);
    bool mp = pp  > 0.5f;
    bool mt = t01 > 0.5f;
    float pl = fabsf(pp - t01);

    // fp16 pixel loss with target-fg mask in the sign bit.
    unsigned short plb = __half_as_ushort(__float2half_rn(pl)) & 0x7FFFu;
    g_plh[gi] = plb | (mt ? 0x8000u : 0u);

    // Row-run labeling: label = index of my run's start lane (<= my lane).
    unsigned mle = 0xffffffffu >> (31 - lx);      // lanes <= me
    unsigned bp  = __ballot_sync(0xffffffffu, mp);
    unsigned bt  = __ballot_sync(0xffffffffu, mt);
    unsigned stp = bp & ~(bp << 1);               // run-start lanes
    unsigned stt = bt & ~(bt << 1);
    lp[l] = mp ? ly * TS + (31 - __clz(stp & mle)) : -1;
    lt[l] = mt ? ly * TS + (31 - __clz(stt & mle)) : -1;
    __syncthreads();

    // Vertical unions only (horizontal handled by run labels).
    if (ly > 0) {
        if (mp && lp[l - TS] >= 0) s_union(lp, l, l - TS);
        if (mt && lt[l - TS] >= 0) s_union(lt, l, l - TS);
    }
    __syncthreads();

    int rp = mp ? s_find(lp, l) : -1;
    int rt = mt ? s_find(lt, l) : -1;
    bool rootp = mp && (rp == l);
    bool roott = mt && (rt == l);

    unsigned balp = __ballot_sync(0xffffffffu, rootp);
    unsigned balt = __ballot_sync(0xffffffffu, roott);
    if (lx == 0) { sWp[ly] = __popc(balp); sWt[ly] = __popc(balt); }
    __syncthreads();

    // Exclusive scan of per-warp root counts; warp 0 = pred, warp 1 = target.
    if (l < 32) {
        int orig = sWp[l], v = orig;
        #pragma unroll
        for (int o = 1; o < 32; o <<= 1) {
            int n = __shfl_up_sync(0xffffffffu, v, o);
            if (l >= o) v += n;
        }
        sWp[l] = v - orig;
        if (l == 31) s_pb = atomicAdd(&g_np, v);
    } else if (l < 64) {
        int k = l - 32;
        int orig = sWt[k], v = orig;
        #pragma unroll
        for (int o = 1; o < 32; o <<= 1) {
            int n = __shfl_up_sync(0xffffffffu, v, o);
            if (k >= o) v += n;
        }
        sWt[k] = v - orig;
        if (k == 31) s_tb = atomicAdd(&g_nt, v);
    }
    __syncthreads();

    // Roots: compute rank, init compact entries, publish rank via lp/lt[l].
    unsigned lmask = (1u << lx) - 1u;
    if (rootp) {
        int rank = sWp[ly] + __popc(balp & lmask);
        int cid  = s_pb + rank;
        lp[l] = rank;
        g_parp[cid] = cid;
        g_smin[cid] = INT_MAX;
        g_smax[cid] = -1;
    }
    if (roott) {
        int rank = sWt[ly] + __popc(balt & lmask);
        lt[l] = rank;
        g_part[s_tb + rank] = s_tb + rank;
    }
    __syncthreads();

    g_locp[gi] = mp ? (unsigned short)lp[rp] : (unsigned short)BG16;
    g_loct[gi] = mt ? (unsigned short)lt[rt] : (unsigned short)BG16;
    if (l == 0) { g_pbase[tileIdx] = s_pb; g_tbase[tileIdx] = s_tb; }
}

// Merge across tile boundaries; one thread = one edge, both masks.
__global__ void k_bmerge() {
    int tid = blockIdx.x * blockDim.x + threadIdx.x;
    if (tid >= NEDGE) return;
    int b = tid / EPI;
    int e = tid % EPI;
    int y, x, ny, nx;
    if (e < EPT) {                       // vertical boundary: (y,x)-(y,x-1)
        int bi = e / HH; y = e % HH;
        x = TS * (bi + 1); ny = y; nx = x - 1;
    } else {                             // horizontal boundary: (y,x)-(y-1,x)
        e -= EPT;
        int bi = e / WW; x = e % WW;
        y = TS * (bi + 1); ny = y - 1; nx = x;
    }
    int idx = b * HWSZ + y * WW + x;
    int n   = b * HWSZ + ny * WW + nx;
    unsigned ap = g_locp[idx], cp = g_locp[n];
    unsigned at = g_loct[idx], ct = g_loct[n];
    int tA = (b * TILES_Y + (y  >> 5)) * TILES_X + (x  >> 5);
    int tC = (b * TILES_Y + (ny >> 5)) * TILES_X + (nx >> 5);

    if (ap != BG16 && cp != BG16)
        uf_union(g_parp, g_pbase[tA] + (int)ap, g_pbase[tC] + (int)cp);
    if (at != BG16 && ct != BG16)
        uf_union(g_part, g_tbase[tA] + (int)at, g_tbase[tC] + (int)ct);
}

// Flatten EVERY live compact entry to its final root. Live sets are exactly
// [0, g_np) and [0, g_nt). One independent short chase per thread (high MLP).
__global__ void k_compress() {
    int np = g_np, nt = g_nt;
    int total = np + nt;
    for (int i = blockIdx.x * blockDim.x + threadIdx.x; i < total;
         i += gridDim.x * blockDim.x) {
        if (i < np) uf_findc(g_parp, i);
        else        uf_findc(g_part, i - np);
    }
}

// 4 pixels/thread: independent 1-hop root loads feed L2-resident min/max
// atomics; identical adjacent pairs deduped before the atomic.
__global__ void k_agg() {
    int v = blockIdx.x * blockDim.x + threadIdx.x;   // exact cover of N4
    ushort4 P = ((const ushort4*)g_locp)[v];
    ushort4 T = ((const ushort4*)g_loct)[v];
    unsigned pv[4] = {P.x, P.y, P.z, P.w};
    unsigned tv[4] = {T.x, T.y, T.z, T.w};

    int i0  = 4 * v;
    int b   = i0 / HWSZ;
    int rem = i0 - b * HWSZ;
    int tile = (b * TILES_Y + ((rem / WW) >> 5)) * TILES_X + ((rem % WW) >> 5);
    int pb = g_pbase[tile], tb = g_tbase[tile];   // all 4 px share one tile

    int prev_rp = -1, prev_rt = -1;
    #pragma unroll
    for (int j = 0; j < 4; j++) {
        if (pv[j] == BG16 || tv[j] == BG16) continue;
        int rp = g_parp[pb + (int)pv[j]];   // 1 hop: flattened
        int rt = g_part[tb + (int)tv[j]];
        if (rp == prev_rp && rt == prev_rt) continue;   // dedup adjacent
        prev_rp = rp; prev_rt = rt;
        atomicMin(&g_smin[rp], rt);
        atomicMax(&g_smax[rp], rt);
    }
}

// Per pred compact ID: resolve merged flag once (L2-resident) so k_loss needs
// only a single independent byte load per candidate pixel.
__global__ void k_mark() {
    int np = g_np;
    for (int i = blockIdx.x * blockDim.x + threadIdx.x; i < np;
         i += gridDim.x * blockDim.x) {
        int r = g_parp[i];               // final root (flattened)
        g_merged[i] = (g_smax[r] > g_smin[r]) ? 1 : 0;
    }
}

// Weighted loss from stored fp16 pl + labels only (18.9MB total), 8 px/thread.
// Fused deterministic final reduction (last-block pattern).
__global__ void k_loss(float* __restrict__ out) {
    __shared__ double sh[256];
    int v = blockIdx.x * blockDim.x + threadIdx.x;   // exact cover of N8
    int i0  = 8 * v;
    int b   = i0 / HWSZ;
    int rem = i0 - b * HWSZ;
    int tile = (b * TILES_Y + ((rem / WW) >> 5)) * TILES_X + ((rem % WW) >> 5);
    int pbase = g_pbase[tile];   // all 8 pixels share one tile (x0 % 8 == 0)

    uint4 PL = ((const uint4*)g_plh)[v];    // 8 halves (sign = target-fg)
    uint4 LP = ((const uint4*)g_locp)[v];   // 8 pred ranks
    unsigned plw[4] = {PL.x, PL.y, PL.z, PL.w};
    unsigned lpw[4] = {LP.x, LP.y, LP.z, LP.w};

    float s = 0.0f;
    #pragma unroll
    for (int q = 0; q < 4; q++) {
        #pragma unroll
        for (int h = 0; h < 2; h++) {
            unsigned bits = (plw[q] >> (16 * h)) & 0xFFFFu;
            unsigned rank = (lpw[q] >> (16 * h)) & 0xFFFFu;
            float pl = __half2float(__ushort_as_half((unsigned short)(bits & 0x7FFFu)));
            bool tfg = (bits & 0x8000u) != 0;
            float w = 1.0f;
            if (rank != BG16 && !tfg && g_merged[pbase + (int)rank]) w = 11.0f;
            s += pl * w;     // <= 8 halves: f32 accumulation exact enough here
        }
    }

    sh[threadIdx.x] = (double)s;
    __syncthreads();
    for (int off = 128; off > 0; off >>= 1) {
        if (threadIdx.x < off) sh[threadIdx.x] += sh[threadIdx.x + off];
        __syncthreads();
    }
    __shared__ bool last;
    if (threadIdx.x == 0) {
        g_psum[blockIdx.x] = sh[0];
        __threadfence();
        last = (atomicAdd(&g_ctr, 1) == (int)gridDim.x - 1);
    }
    __syncthreads();

    if (last) {
        double s2 = 0.0;
        for (int k = 0; k < LOSS_BLOCKS / 256; k++)          // fixed order
            s2 += g_psum[threadIdx.x + 256 * k];
        sh[threadIdx.x] = s2;
        __syncthreads();
        for (int off = 128; off > 0; off >>= 1) {
            if (threadIdx.x < off) sh[threadIdx.x] += sh[threadIdx.x + off];
            __syncthreads();
        }
        if (threadIdx.x == 0) {
            out[0] = (float)(sh[0] / (double)NTOT);
            g_ctr = 0;                                       // reset for replay
        }
    }
}

// ---------------------------------------------------------------------------
extern "C" void kernel_launch(void* const* d_in, const int* in_sizes, int n_in,
                              void* d_out, int out_size) {
    const float* pred   = (const float*)d_in[0];
    const float* target = (const float*)d_in[1];
    float* out = (float*)d_out;

    k_flag<<<FLAG_BLOCKS, 256>>>((const float4*)pred);
    k_tile<<<dim3(TILES_X, TILES_Y, BB), dim3(TS, TS)>>>(pred, target);
    k_bmerge<<<(NEDGE + 255) / 256, 256>>>();
    k_compress<<<COMP_BLOCKS, 256>>>();
    k_agg<<<N4 / 256, 256>>>();
    k_mark<<<MARK_BLOCKS, 256>>>();
    k_loss<<<LOSS_BLOCKS, 256>>>(out);
}